// round 9
// baseline (speedup 1.0000x reference)
#include <cuda_runtime.h>
#include <cuda_bf16.h>

#define NB 8
#define NC 256
#define HW 16384            // 128*128
#define HW4 4096            // HW / 4
#define NK 64
#define SMOOTH 1e-6f

// Scratch (device globals: allocation-free per harness rules)
__device__ float g_score[NB * NC];
__device__ int   g_sel[NB * NK];
__device__ float g_attn[NB * HW];

// ---------------------------------------------------------------------------
// Kernel A: per-channel uncertainty score (mean over H*W).
// grid = NB*NC blocks, 256 threads; each thread reduces 64 elems (16 float4).
// ---------------------------------------------------------------------------
__global__ void __launch_bounds__(256) score_kernel(const float* __restrict__ x) {
    const int bc  = blockIdx.x;                       // 0 .. NB*NC-1
    const int tid = threadIdx.x;
    const float4* xp = (const float4*)(x + (size_t)bc * HW);

    float sum = 0.0f;
#pragma unroll
    for (int i = 0; i < 16; i++) {
        float4 v = xp[i * 256 + tid];
        {
            float s = 1.0f / (1.0f + expf(-v.x));
            sum += -s * logf(s + SMOOTH);
        }
        {
            float s = 1.0f / (1.0f + expf(-v.y));
            sum += -s * logf(s + SMOOTH);
        }
        {
            float s = 1.0f / (1.0f + expf(-v.z));
            sum += -s * logf(s + SMOOTH);
        }
        {
            float s = 1.0f / (1.0f + expf(-v.w));
            sum += -s * logf(s + SMOOTH);
        }
    }

    // warp reduce
#pragma unroll
    for (int off = 16; off > 0; off >>= 1)
        sum += __shfl_down_sync(0xFFFFFFFFu, sum, off);

    __shared__ float warp_sums[8];
    if ((tid & 31) == 0) warp_sums[tid >> 5] = sum;
    __syncthreads();
    if (tid == 0) {
        float t = 0.0f;
#pragma unroll
        for (int wv = 0; wv < 8; wv++) t += warp_sums[wv];
        g_score[bc] = t * (1.0f / (float)HW);
    }
}

// ---------------------------------------------------------------------------
// Kernel B: per-batch rank-sort -> indices of the NK smallest scores,
// ascending (== jax.lax.top_k(-score): descending -score, ties -> lower idx).
// grid = NB blocks, 256 threads.
// ---------------------------------------------------------------------------
__global__ void __launch_bounds__(256) select_kernel() {
    const int b = blockIdx.x;
    const int t = threadIdx.x;
    __shared__ float s[NC];
    s[t] = g_score[b * NC + t];
    __syncthreads();

    const float my = s[t];
    int rank = 0;
#pragma unroll 8
    for (int j = 0; j < NC; j++) {
        float v = s[j];
        rank += (v < my) || (v == my && j < t);
    }
    if (rank < NK) g_sel[b * NK + rank] = t;
}

// ---------------------------------------------------------------------------
// Kernel C: attn[b,p] = sigmoid( sum_k x[b, sel[b,k], p] * w[k] + bias ).
// grid = (HW4/256, NB) = (16, 8); 256 threads, one float4 (4 positions) each.
// ---------------------------------------------------------------------------
__global__ void __launch_bounds__(256) attn_kernel(const float* __restrict__ x,
                                                   const float* __restrict__ w,
                                                   const float* __restrict__ bias) {
    __shared__ int   sel[NK];
    __shared__ float ws[NK];
    const int b = blockIdx.y;
    const int t = threadIdx.x;
    if (t < NK) {
        sel[t] = g_sel[b * NK + t];
        ws[t]  = w[t];
    }
    __syncthreads();

    const int p4 = blockIdx.x * 256 + t;   // float4 index within HW4
    const float4* xb = (const float4*)x + (size_t)b * NC * HW4;

    float4 acc = make_float4(0.f, 0.f, 0.f, 0.f);
#pragma unroll 8
    for (int k = 0; k < NK; k++) {
        float4 v = xb[(size_t)sel[k] * HW4 + p4];
        float wk = ws[k];
        acc.x += v.x * wk;
        acc.y += v.y * wk;
        acc.z += v.z * wk;
        acc.w += v.w * wk;
    }
    const float bb = bias[0];
    float4 a;
    a.x = 1.0f / (1.0f + expf(-(acc.x + bb)));
    a.y = 1.0f / (1.0f + expf(-(acc.y + bb)));
    a.z = 1.0f / (1.0f + expf(-(acc.z + bb)));
    a.w = 1.0f / (1.0f + expf(-(acc.w + bb)));
    ((float4*)g_attn)[b * HW4 + p4] = a;
}

// ---------------------------------------------------------------------------
// Kernel D: out[b,c,p] = x[b,c,p] * attn[b,p].
// grid = NB*NC*HW4 / 256 = 32768 blocks, 256 threads, one float4 each.
// attn (512 KB total) is L2-resident across the 256x channel reuse.
// ---------------------------------------------------------------------------
__global__ void __launch_bounds__(256) mul_kernel(const float* __restrict__ x,
                                                  float* __restrict__ out) {
    const int i  = blockIdx.x * 256 + threadIdx.x;   // float4 index, < 8388608
    const int p4 = i & (HW4 - 1);
    const int b  = i >> 20;                          // i / (NC*HW4) = i / 1048576
    float4 v = ((const float4*)x)[i];
    float4 a = ((const float4*)g_attn)[(b << 12) + p4];
    float4 o;
    o.x = v.x * a.x;
    o.y = v.y * a.y;
    o.z = v.z * a.z;
    o.w = v.w * a.w;
    ((float4*)out)[i] = o;
}

// ---------------------------------------------------------------------------
extern "C" void kernel_launch(void* const* d_in, const int* in_sizes, int n_in,
                              void* d_out, int out_size) {
    const float* x    = (const float*)d_in[0];   // [8,256,128,128] fp32
    const float* w    = (const float*)d_in[1];   // [64]
    const float* bias = (const float*)d_in[2];   // [1]
    float* out = (float*)d_out;

    score_kernel<<<NB * NC, 256>>>(x);
    select_kernel<<<NB, 256>>>();
    attn_kernel<<<dim3(HW4 / 256, NB), 256>>>(x, w, bias);
    mul_kernel<<<(NB * NC * HW4) / 256, 256>>>(x, out);
}

// round 10
// speedup vs baseline: 1.0037x; 1.0037x over previous
#include <cuda_runtime.h>
#include <cuda_bf16.h>

#define NB 8
#define NC 256
#define HW 16384            // 128*128
#define HW4 4096            // HW / 4
#define NK 64
#define SMOOTH 1e-6f

// Scratch (device globals: allocation-free per harness rules)
__device__ float g_score[NB * NC];
__device__ int   g_sel[NB * NK];
__device__ float g_attn[NB * HW];

// ---------------------------------------------------------------------------
// Kernel A: per-channel uncertainty score (mean over H*W).
// grid = NB*NC blocks, 256 threads; each thread reduces 64 elems (16 float4).
// ---------------------------------------------------------------------------
__global__ void __launch_bounds__(256) score_kernel(const float* __restrict__ x) {
    const int bc  = blockIdx.x;                       // 0 .. NB*NC-1
    const int tid = threadIdx.x;
    const float4* xp = (const float4*)(x + (size_t)bc * HW);

    float sum = 0.0f;
#pragma unroll
    for (int i = 0; i < 16; i++) {
        float4 v = xp[i * 256 + tid];
        {
            float s = 1.0f / (1.0f + expf(-v.x));
            sum += -s * logf(s + SMOOTH);
        }
        {
            float s = 1.0f / (1.0f + expf(-v.y));
            sum += -s * logf(s + SMOOTH);
        }
        {
            float s = 1.0f / (1.0f + expf(-v.z));
            sum += -s * logf(s + SMOOTH);
        }
        {
            float s = 1.0f / (1.0f + expf(-v.w));
            sum += -s * logf(s + SMOOTH);
        }
    }

    // warp reduce
#pragma unroll
    for (int off = 16; off > 0; off >>= 1)
        sum += __shfl_down_sync(0xFFFFFFFFu, sum, off);

    __shared__ float warp_sums[8];
    if ((tid & 31) == 0) warp_sums[tid >> 5] = sum;
    __syncthreads();
    if (tid == 0) {
        float t = 0.0f;
#pragma unroll
        for (int wv = 0; wv < 8; wv++) t += warp_sums[wv];
        g_score[bc] = t * (1.0f / (float)HW);
    }
}

// ---------------------------------------------------------------------------
// Kernel B: per-batch rank-sort -> indices of the NK smallest scores,
// ascending (== jax.lax.top_k(-score): descending -score, ties -> lower idx).
// grid = NB blocks, 256 threads.
// ---------------------------------------------------------------------------
__global__ void __launch_bounds__(256) select_kernel() {
    const int b = blockIdx.x;
    const int t = threadIdx.x;
    __shared__ float s[NC];
    s[t] = g_score[b * NC + t];
    __syncthreads();

    const float my = s[t];
    int rank = 0;
#pragma unroll 8
    for (int j = 0; j < NC; j++) {
        float v = s[j];
        rank += (v < my) || (v == my && j < t);
    }
    if (rank < NK) g_sel[b * NK + rank] = t;
}

// ---------------------------------------------------------------------------
// Kernel C: attn[b,p] = sigmoid( sum_k x[b, sel[b,k], p] * w[k] + bias ).
// grid = (HW4/256, NB) = (16, 8); 256 threads, one float4 (4 positions) each.
// ---------------------------------------------------------------------------
__global__ void __launch_bounds__(256) attn_kernel(const float* __restrict__ x,
                                                   const float* __restrict__ w,
                                                   const float* __restrict__ bias) {
    __shared__ int   sel[NK];
    __shared__ float ws[NK];
    const int b = blockIdx.y;
    const int t = threadIdx.x;
    if (t < NK) {
        sel[t] = g_sel[b * NK + t];
        ws[t]  = w[t];
    }
    __syncthreads();

    const int p4 = blockIdx.x * 256 + t;   // float4 index within HW4
    const float4* xb = (const float4*)x + (size_t)b * NC * HW4;

    float4 acc = make_float4(0.f, 0.f, 0.f, 0.f);
#pragma unroll 8
    for (int k = 0; k < NK; k++) {
        float4 v = xb[(size_t)sel[k] * HW4 + p4];
        float wk = ws[k];
        acc.x += v.x * wk;
        acc.y += v.y * wk;
        acc.z += v.z * wk;
        acc.w += v.w * wk;
    }
    const float bb = bias[0];
    float4 a;
    a.x = 1.0f / (1.0f + expf(-(acc.x + bb)));
    a.y = 1.0f / (1.0f + expf(-(acc.y + bb)));
    a.z = 1.0f / (1.0f + expf(-(acc.z + bb)));
    a.w = 1.0f / (1.0f + expf(-(acc.w + bb)));
    ((float4*)g_attn)[b * HW4 + p4] = a;
}

// ---------------------------------------------------------------------------
// Kernel D: out[b,c,p] = x[b,c,p] * attn[b,p].
// grid = NB*NC*HW4 / 256 = 32768 blocks, 256 threads, one float4 each.
// attn (512 KB total) is L2-resident across the 256x channel reuse.
// ---------------------------------------------------------------------------
__global__ void __launch_bounds__(256) mul_kernel(const float* __restrict__ x,
                                                  float* __restrict__ out) {
    const int i  = blockIdx.x * 256 + threadIdx.x;   // float4 index, < 8388608
    const int p4 = i & (HW4 - 1);
    const int b  = i >> 20;                          // i / (NC*HW4) = i / 1048576
    float4 v = ((const float4*)x)[i];
    float4 a = ((const float4*)g_attn)[(b << 12) + p4];
    float4 o;
    o.x = v.x * a.x;
    o.y = v.y * a.y;
    o.z = v.z * a.z;
    o.w = v.w * a.w;
    ((float4*)out)[i] = o;
}

// ---------------------------------------------------------------------------
extern "C" void kernel_launch(void* const* d_in, const int* in_sizes, int n_in,
                              void* d_out, int out_size) {
    const float* x    = (const float*)d_in[0];   // [8,256,128,128] fp32
    const float* w    = (const float*)d_in[1];   // [64]
    const float* bias = (const float*)d_in[2];   // [1]
    float* out = (float*)d_out;

    score_kernel<<<NB * NC, 256>>>(x);
    select_kernel<<<NB, 256>>>();
    attn_kernel<<<dim3(HW4 / 256, NB), 256>>>(x, w, bias);
    mul_kernel<<<(NB * NC * HW4) / 256, 256>>>(x, out);
}

// round 11
// speedup vs baseline: 1.4828x; 1.4773x over previous
#include <cuda_runtime.h>
#include <cuda_bf16.h>

#define NB 8
#define NC 256
#define HW 16384            // 128*128
#define HW4 4096            // HW / 4
#define NK 64
#define SMOOTH 1e-6f

// Scratch (device globals: allocation-free per harness rules)
__device__ float g_score[NB * NC];
__device__ int   g_sel[NB * NK];
__device__ float g_attn[NB * HW];

// ---------------------------------------------------------------------------
// Kernel A: per-channel uncertainty score (mean over H*W), fast-math version.
// Score is only consumed by the rank-sort; MUFU intrinsic error (~1e-9 in the
// channel mean after averaging) is far below adjacent score gaps (~8e-6).
// grid = NB*NC blocks, 256 threads; each thread reduces 64 elems (16 float4).
// ---------------------------------------------------------------------------
__device__ __forceinline__ float unc(float v) {
    float ex = __expf(-v);
    float s  = __fdividef(1.0f, 1.0f + ex);
    return -s * __logf(s + SMOOTH);
}

__global__ void __launch_bounds__(256) score_kernel(const float* __restrict__ x) {
    const int bc  = blockIdx.x;                       // 0 .. NB*NC-1
    const int tid = threadIdx.x;
    const float4* xp = (const float4*)(x + (size_t)bc * HW);

    float sum = 0.0f;
#pragma unroll
    for (int i = 0; i < 16; i++) {
        float4 v = __ldcs(&xp[i * 256 + tid]);
        sum += unc(v.x);
        sum += unc(v.y);
        sum += unc(v.z);
        sum += unc(v.w);
    }

    // warp reduce
#pragma unroll
    for (int off = 16; off > 0; off >>= 1)
        sum += __shfl_down_sync(0xFFFFFFFFu, sum, off);

    __shared__ float warp_sums[8];
    if ((tid & 31) == 0) warp_sums[tid >> 5] = sum;
    __syncthreads();
    if (tid == 0) {
        float t = 0.0f;
#pragma unroll
        for (int wv = 0; wv < 8; wv++) t += warp_sums[wv];
        g_score[bc] = t * (1.0f / (float)HW);
    }
}

// ---------------------------------------------------------------------------
// Kernel B: per-batch rank-sort -> indices of the NK smallest scores,
// ascending (== jax.lax.top_k(-score): descending -score, ties -> lower idx).
// grid = NB blocks, 256 threads.
// ---------------------------------------------------------------------------
__global__ void __launch_bounds__(256) select_kernel() {
    const int b = blockIdx.x;
    const int t = threadIdx.x;
    __shared__ float s[NC];
    s[t] = g_score[b * NC + t];
    __syncthreads();

    const float my = s[t];
    int rank = 0;
#pragma unroll 8
    for (int j = 0; j < NC; j++) {
        float v = s[j];
        rank += (v < my) || (v == my && j < t);
    }
    if (rank < NK) g_sel[b * NK + rank] = t;
}

// ---------------------------------------------------------------------------
// Kernel C: attn[b,p] = sigmoid( sum_k x[b, sel[b,k], p] * w[k] + bias ).
// grid = (HW4/64, NB) = (64, 8) = 512 blocks; 256 threads.
// Block covers 64 float4 positions; the K=64 loop is split across 4 thread
// groups of 16 k's each, partial sums reduced through shared memory.
// ---------------------------------------------------------------------------
__global__ void __launch_bounds__(256) attn_kernel(const float* __restrict__ x,
                                                   const float* __restrict__ w,
                                                   const float* __restrict__ bias) {
    __shared__ int    sel[NK];
    __shared__ float  ws[NK];
    __shared__ float4 red[256];
    const int b  = blockIdx.y;
    const int t  = threadIdx.x;
    const int pi = t & 63;          // position within block's 64-float4 tile
    const int kg = t >> 6;          // k-group 0..3
    if (t < NK) {
        sel[t] = g_sel[b * NK + t];
        ws[t]  = w[t];
    }
    __syncthreads();

    const int p4 = blockIdx.x * 64 + pi;
    const float4* xb = (const float4*)x + (size_t)b * NC * HW4;

    float4 acc = make_float4(0.f, 0.f, 0.f, 0.f);
    const int k0 = kg * 16;
#pragma unroll
    for (int kk = 0; kk < 16; kk++) {
        const int k = k0 + kk;
        float4 v = __ldcs(&xb[(size_t)sel[k] * HW4 + p4]);
        float wk = ws[k];
        acc.x += v.x * wk;
        acc.y += v.y * wk;
        acc.z += v.z * wk;
        acc.w += v.w * wk;
    }
    red[t] = acc;
    __syncthreads();

    if (kg == 0) {
        float4 a1 = red[t + 64], a2 = red[t + 128], a3 = red[t + 192];
        acc.x += a1.x + a2.x + a3.x;
        acc.y += a1.y + a2.y + a3.y;
        acc.z += a1.z + a2.z + a3.z;
        acc.w += a1.w + a2.w + a3.w;
        const float bb = bias[0];
        float4 a;
        a.x = 1.0f / (1.0f + expf(-(acc.x + bb)));
        a.y = 1.0f / (1.0f + expf(-(acc.y + bb)));
        a.z = 1.0f / (1.0f + expf(-(acc.z + bb)));
        a.w = 1.0f / (1.0f + expf(-(acc.w + bb)));
        ((float4*)g_attn)[b * HW4 + p4] = a;
    }
}

// ---------------------------------------------------------------------------
// Kernel D: out[b,c,p] = x[b,c,p] * attn[b,p].
// grid = 16384 blocks, 256 threads, two float4 each (ILP=2).
// x / out are single-use streams (__ldcs/__stcs); attn (512 KB) stays in L2.
// ---------------------------------------------------------------------------
__global__ void __launch_bounds__(256) mul_kernel(const float* __restrict__ x,
                                                  float* __restrict__ out) {
    const int i0 = blockIdx.x * 512 + threadIdx.x;   // float4 index
    const int i1 = i0 + 256;

    float4 v0 = __ldcs(((const float4*)x) + i0);
    float4 v1 = __ldcs(((const float4*)x) + i1);

    const int p40 = i0 & (HW4 - 1);
    const int b0  = i0 >> 20;                        // i / (NC*HW4)
    const int p41 = i1 & (HW4 - 1);
    const int b1  = i1 >> 20;

    float4 a0 = ((const float4*)g_attn)[(b0 << 12) + p40];
    float4 a1 = ((const float4*)g_attn)[(b1 << 12) + p41];

    float4 o0, o1;
    o0.x = v0.x * a0.x; o0.y = v0.y * a0.y; o0.z = v0.z * a0.z; o0.w = v0.w * a0.w;
    o1.x = v1.x * a1.x; o1.y = v1.y * a1.y; o1.z = v1.z * a1.z; o1.w = v1.w * a1.w;

    __stcs(((float4*)out) + i0, o0);
    __stcs(((float4*)out) + i1, o1);
}

// ---------------------------------------------------------------------------
extern "C" void kernel_launch(void* const* d_in, const int* in_sizes, int n_in,
                              void* d_out, int out_size) {
    const float* x    = (const float*)d_in[0];   // [8,256,128,128] fp32
    const float* w    = (const float*)d_in[1];   // [64]
    const float* bias = (const float*)d_in[2];   // [1]
    float* out = (float*)d_out;

    score_kernel<<<NB * NC, 256>>>(x);
    select_kernel<<<NB, 256>>>();
    attn_kernel<<<dim3(HW4 / 64, NB), 256>>>(x, w, bias);
    mul_kernel<<<16384, 256>>>(x, out);
}